// round 5
// baseline (speedup 1.0000x reference)
#include <cuda_runtime.h>
#include <stdint.h>

// ---------------------------------------------------------------------------
// ToDenseBEVConvolution: out[b][c][x][y] += sum_i features[n][i] * K[z_n][i][c]
// C_IN = C_OUT = 64, 32 kernel matrices, BEV 256x256, batch<=4, N = 100000.
//
// Pipeline (5 launches, graph-capturable, allocation-free, NO global atomics
// on the output and NO output zero-fill):
//   k_hist    : per-block histograms over z (32) and (b,x) (1024) buckets
//   k_scan    : single block: offsets for both sorts + GEMM tile descriptors
//   k_scatter : counting-sort scatter (z-order: point idx; bx-order: key)
//   k_gemm    : 128-point z-tiles, 8x8 register GEMM -> inter[zpos][64]
//   k_out     : one block per (b,x): accumulate bucket points in SMEM
//               (y,c) tile, write out[b][:,x,:] fully (covers zeros too)
// ---------------------------------------------------------------------------

#define C_IN    64
#define C_OUT   64
#define BEV_Y   256
#define BEV_XY  (256 * 256)
#define TILE_P  128
#define NZ      32
#define NBX     1024
#define N_MAX   (1 << 17)
#define B_MAX   224
#define TILES_MAX (N_MAX / TILE_P + NZ + 2)
#define FSN     132

#define SMEM_GEMM_BYTES ((4096 + 64 * FSN) * 4)
#define SMEM_OUT_BYTES  (256 * 65 * 4)

// ---- scratch (static device globals) ----
__device__ int   g_blkz[B_MAX * NZ];
__device__ int   g_offz[B_MAX * NZ];
__device__ int   g_blkbx[B_MAX * NBX];
__device__ int   g_offbx[B_MAX * NBX];
__device__ int   g_bxstart[NBX];
__device__ int   g_bxcnt[NBX];
__device__ int   g_ntiles;
__device__ int   g_pidx[N_MAX];            // z-sorted -> original point index
__device__ int   g_okey[N_MAX];            // bx-sorted -> (zpos<<8) | y
__device__ float g_inter[(size_t)N_MAX * C_OUT];   // 32 MB
__device__ int   g_tile_z[TILES_MAX];
__device__ int   g_tile_start[TILES_MAX];
__device__ int   g_tile_cnt[TILES_MAX];

// ---------------------------------------------------------------------------
__device__ __forceinline__ int detect_is64_warp(const void* coords) {
    const long long* c = (const long long*)coords;
    bool hz = ((c[threadIdx.x & 31] >> 32) == 0);
    unsigned m = __ballot_sync(0xffffffffu, hz);
    return (m == 0xffffffffu) ? 1 : 0;
}

__device__ __forceinline__ void load_coord4(const void* coords, int is64, int i,
                                            int& x, int& z, int& y, int& b) {
    if (is64) {
        const long long* p = (const long long*)coords + 4ll * i;
        x = (int)p[0]; z = (int)p[1]; y = (int)p[2]; b = (int)p[3];
    } else {
        const int* p = (const int*)coords + 4 * i;
        x = p[0]; z = p[1]; y = p[2]; b = p[3];
    }
}

// ---------------------------------------------------------------------------
// Dual histogram: z buckets (32) and bx buckets (1024). SMEM atomics only.
// ---------------------------------------------------------------------------
__global__ void k_hist(const void* coords, const int* stride_p, int n, int chunk) {
    __shared__ int hz[NZ];
    __shared__ int hbx[NBX];
    __shared__ int s_is64;
    int tid = threadIdx.x;
    if (tid < NZ) hz[tid] = 0;
    for (int t = tid; t < NBX; t += 256) hbx[t] = 0;
    if (tid < 32) {
        int v = detect_is64_warp(coords);
        if (tid == 0) s_is64 = v;
    }
    __syncthreads();

    int stride = max(*stride_p, 1);
    int lo = blockIdx.x * chunk;
    int hi = min(lo + chunk, n);
    int is64 = s_is64;
    for (int i = lo + tid; i < hi; i += 256) {
        int x, z, y, b;
        load_coord4(coords, is64, i, x, z, y, b);
        atomicAdd(&hz[z / stride], 1);
        int bx = (b << 8) | (x / stride);
        atomicAdd(&hbx[bx & (NBX - 1)], 1);
    }
    __syncthreads();
    if (tid < NZ) g_blkz[blockIdx.x * NZ + tid] = hz[tid];
    for (int t = tid; t < NBX; t += 256)
        g_blkbx[blockIdx.x * NBX + t] = hbx[t];
}

// ---------------------------------------------------------------------------
// Single-block scan for both sorts + tile descriptors. 1024 threads.
// ---------------------------------------------------------------------------
__global__ void k_scan(int B) {
    __shared__ int s[B_MAX * NZ];          // 28 KB
    __shared__ int bstart[NZ];
    __shared__ int bcnt[NZ];
    __shared__ int tstart[NZ + 1];
    __shared__ int wsum[32];
    int tid = threadIdx.x;

    // ---- part A: z sort ----
    for (int t = tid; t < B * NZ; t += 1024) s[t] = g_blkz[t];
    __syncthreads();

    if (tid < NZ) {
        int z = tid, run = 0;
        for (int b = 0; b < B; b++) {
            int v = s[b * NZ + z];
            s[b * NZ + z] = run;
            run += v;
        }
        bcnt[z] = run;
    }
    __syncthreads();

    if (tid < 32) {
        int z = tid;
        int c  = bcnt[z];
        int tl = (c + TILE_P - 1) / TILE_P;
        int co = c, to = tl;
        #pragma unroll
        for (int d = 1; d < 32; d <<= 1) {
            int v = __shfl_up_sync(0xffffffffu, co, d);
            int w = __shfl_up_sync(0xffffffffu, to, d);
            if (z >= d) { co += v; to += w; }
        }
        bstart[z] = co - c;
        tstart[z] = to - tl;
        if (z == 31) { tstart[NZ] = to; g_ntiles = to; }
    }
    __syncthreads();

    for (int t = tid; t < B * NZ; t += 1024) {
        int z = t & (NZ - 1);
        g_offz[t] = s[t] + bstart[z];
    }

    int ntiles = tstart[NZ];
    for (int t = tid; t < ntiles; t += 1024) {
        int lo = 0, hi = NZ - 1;
        while (lo < hi) {
            int mid = (lo + hi + 1) >> 1;
            if (tstart[mid] <= t) lo = mid; else hi = mid - 1;
        }
        int local = t - tstart[lo];
        g_tile_z[t]     = lo;
        g_tile_start[t] = bstart[lo] + local * TILE_P;
        g_tile_cnt[t]   = min(TILE_P, bcnt[lo] - local * TILE_P);
    }

    // ---- part B: bx sort (thread tid owns bucket tid) ----
    int run = 0;
    for (int b = 0; b < B; b++) {
        int v = g_blkbx[b * NBX + tid];
        g_offbx[b * NBX + tid] = run;
        run += v;
    }
    g_bxcnt[tid] = run;

    // block-wide exclusive scan of 1024 bucket counts
    int lane = tid & 31, w = tid >> 5;
    int inc = run;
    #pragma unroll
    for (int d = 1; d < 32; d <<= 1) {
        int v = __shfl_up_sync(0xffffffffu, inc, d);
        if (lane >= d) inc += v;
    }
    if (lane == 31) wsum[w] = inc;
    __syncthreads();
    if (w == 0) {
        int v = wsum[lane];
        int iv = v;
        #pragma unroll
        for (int d = 1; d < 32; d <<= 1) {
            int u = __shfl_up_sync(0xffffffffu, iv, d);
            if (lane >= d) iv += u;
        }
        wsum[lane] = iv - v;   // exclusive
    }
    __syncthreads();
    g_bxstart[tid] = wsum[w] + inc - run;
}

// ---------------------------------------------------------------------------
// Counting-sort scatter for both orders.
// ---------------------------------------------------------------------------
__global__ void k_scatter(const void* coords, const int* stride_p, int n, int chunk) {
    __shared__ int cur_z[NZ];
    __shared__ int cur_bx[NBX];
    __shared__ int s_is64;
    int tid = threadIdx.x;
    if (tid < NZ) cur_z[tid] = g_offz[blockIdx.x * NZ + tid];
    for (int t = tid; t < NBX; t += 256)
        cur_bx[t] = g_bxstart[t] + g_offbx[blockIdx.x * NBX + t];
    if (tid < 32) {
        int v = detect_is64_warp(coords);
        if (tid == 0) s_is64 = v;
    }
    __syncthreads();

    int stride = max(*stride_p, 1);
    int lo = blockIdx.x * chunk;
    int hi = min(lo + chunk, n);
    int is64 = s_is64;
    for (int i = lo + tid; i < hi; i += 256) {
        int x, z, y, b;
        load_coord4(coords, is64, i, x, z, y, b);
        int zq = z / stride;
        int xq = x / stride;
        int yq = y / stride;
        int bx = ((b << 8) | xq) & (NBX - 1);

        int zpos = atomicAdd(&cur_z[zq], 1);
        g_pidx[zpos] = i;
        int bxpos = atomicAdd(&cur_bx[bx], 1);
        g_okey[bxpos] = (zpos << 8) | (yq & 255);
    }
}

// ---------------------------------------------------------------------------
// GEMM: one block = one tile of up to 128 points sharing kernel z.
// 128 threads, 8x8 register block, coalesced float4 stores into g_inter.
// ---------------------------------------------------------------------------
__global__ __launch_bounds__(128, 4)
void k_gemm(const float* __restrict__ features,
            const float* __restrict__ kern) {
    int tile = blockIdx.x;
    if (tile >= g_ntiles) return;

    extern __shared__ float smem[];
    float* Ks = smem;                 // [64][64]
    float* Fs = smem + 4096;          // [64][FSN]

    int tid   = threadIdx.x;
    int z     = g_tile_z[tile];
    int start = g_tile_start[tile];
    int cnt   = g_tile_cnt[tile];

    bool valid = tid < cnt;
    int pidx = valid ? g_pidx[start + tid] : 0;

    {
        const float4* k4 = (const float4*)(kern + (size_t)z * C_IN * C_OUT);
        float4* ks4 = (float4*)Ks;
        #pragma unroll
        for (int t = 0; t < 8; t++) ks4[tid + t * 128] = k4[tid + t * 128];
    }
    {
        const float4* frow = (const float4*)(features + (size_t)pidx * C_IN);
        #pragma unroll
        for (int g = 0; g < 16; g++) {
            float4 f = valid ? frow[g] : make_float4(0.f, 0.f, 0.f, 0.f);
            int r = g * 4;
            Fs[(r + 0) * FSN + tid] = f.x;
            Fs[(r + 1) * FSN + tid] = f.y;
            Fs[(r + 2) * FSN + tid] = f.z;
            Fs[(r + 3) * FSN + tid] = f.w;
        }
    }
    __syncthreads();

    int tc = tid & 7;     // channel group (8 x 8 channels)
    int tp = tid >> 3;    // point group  (16 x 8 points)

    float acc[8][8];
    #pragma unroll
    for (int a = 0; a < 8; a++)
        #pragma unroll
        for (int c = 0; c < 8; c++) acc[a][c] = 0.f;

    const float4* fsA = (const float4*)&Fs[tp * 8];
    const float4* ksB = (const float4*)&Ks[tc * 8];

    #pragma unroll 8
    for (int i = 0; i < C_IN; i++) {
        float4 a0 = fsA[i * (FSN / 4)];
        float4 a1 = fsA[i * (FSN / 4) + 1];
        float4 b0 = ksB[i * (C_OUT / 4)];
        float4 b1 = ksB[i * (C_OUT / 4) + 1];
        float av[8] = {a0.x, a0.y, a0.z, a0.w, a1.x, a1.y, a1.z, a1.w};
        float bv[8] = {b0.x, b0.y, b0.z, b0.w, b1.x, b1.y, b1.z, b1.w};
        #pragma unroll
        for (int p = 0; p < 8; p++)
            #pragma unroll
            for (int c = 0; c < 8; c++)
                acc[p][c] += av[p] * bv[c];
    }

    // coalesced stores: point row 256B covered by 8 threads x 2 float4
    #pragma unroll
    for (int pp = 0; pp < 8; pp++) {
        int p = tp * 8 + pp;
        if (p >= cnt) continue;
        float* row = &g_inter[(size_t)(start + p) * C_OUT + tc * 8];
        ((float4*)row)[0] = make_float4(acc[pp][0], acc[pp][1], acc[pp][2], acc[pp][3]);
        ((float4*)row)[1] = make_float4(acc[pp][4], acc[pp][5], acc[pp][6], acc[pp][7]);
    }
}

// ---------------------------------------------------------------------------
// Output: one block per (b,x). Accumulate bucket points into SMEM (y,c) tile
// (smem atomics; collisions rare), then write out[b][:,x,:] coalesced.
// Covers every output element -> no zero-fill pass needed.
// ---------------------------------------------------------------------------
__global__ __launch_bounds__(256, 3)
void k_out(float* __restrict__ out) {
    extern __shared__ float acc[];    // [256][65]
    int tid = threadIdx.x;
    int bb  = blockIdx.x;
    int b   = bb >> 8;
    int x   = bb & 255;

    for (int i = tid; i < 256 * 65; i += 256) acc[i] = 0.f;
    __syncthreads();

    int start = g_bxstart[bb];
    int cnt   = g_bxcnt[bb];
    int c = tid & 63;
    int g = tid >> 6;                 // 4 groups of 64 channels
    for (int p = start + g; p < start + cnt; p += 4) {
        int key  = g_okey[p];
        int zpos = key >> 8;
        int y    = key & 255;
        float v  = g_inter[(size_t)zpos * C_OUT + c];
        atomicAdd(&acc[y * 65 + c], v);
    }
    __syncthreads();

    size_t outbase = ((size_t)b * C_OUT) * BEV_XY + (size_t)x * 256;
    #pragma unroll 4
    for (int k = 0; k < 64; k++)
        out[outbase + (size_t)k * BEV_XY + tid] = acc[tid * 65 + k];
}

// ---------------------------------------------------------------------------
extern "C" void kernel_launch(void* const* d_in, const int* in_sizes, int n_in,
                              void* d_out, int out_size) {
    const float* features = (const float*)d_in[0];
    const float* kern     = (const float*)d_in[1];
    const void*  coords   = (const void*)d_in[2];
    const int*   stride_p = (const int*)d_in[3];
    float* out = (float*)d_out;

    int n = in_sizes[0] / C_IN;
    if (n > N_MAX) n = N_MAX;
    if (n < 1) return;

    int B = (n + 255) / 256;
    if (B > B_MAX) B = B_MAX;
    if (B < 1) B = 1;
    int chunk = (((n + B - 1) / B) + 255) & ~255;
    B = (n + chunk - 1) / chunk;

    static int attr_set = 0;
    if (!attr_set) {
        cudaFuncSetAttribute(k_gemm, cudaFuncAttributeMaxDynamicSharedMemorySize,
                             SMEM_GEMM_BYTES);
        cudaFuncSetAttribute(k_out, cudaFuncAttributeMaxDynamicSharedMemorySize,
                             SMEM_OUT_BYTES);
        attr_set = 1;
    }

    // number of (b,x) buckets = out elements / (64 channels * 256 y)
    int nbx = out_size / (C_OUT * 256);
    if (nbx > NBX) nbx = NBX;

    k_hist<<<B, 256>>>(coords, stride_p, n, chunk);
    k_scan<<<1, 1024>>>(B);
    k_scatter<<<B, 256>>>(coords, stride_p, n, chunk);

    int max_tiles = n / TILE_P + NZ + 1;
    k_gemm<<<max_tiles, 128, SMEM_GEMM_BYTES>>>(features, kern);
    k_out<<<nbx, 256, SMEM_OUT_BYTES>>>(out);
}

// round 6
// speedup vs baseline: 1.2404x; 1.2404x over previous
#include <cuda_runtime.h>
#include <stdint.h>

// ---------------------------------------------------------------------------
// ToDenseBEVConvolution: out[b][c][x][y] += sum_i features[n][i] * K[z_n][i][c]
// C_IN = C_OUT = 64, 32 kernel matrices, BEV 256x256, batch<=4, N = 100000.
//
// Pipeline (5 launches, graph-capturable, allocation-free, no output atomics,
// no output zero-fill):
//   k_hist    : per-block histograms over z (32) and (b,x) (1024) buckets
//   k_scan    : single block: offsets for both sorts + GEMM tile descriptors
//   k_scatter : counting-sort scatter (z-order: point idx; bx-order: key)
//   k_gemm    : 128-point z-tiles, 8x8 register GEMM -> inter[zpos][64]
//   k_out     : one block per (b,x,c-half): SMEM-staged keys + MLP-4 batched
//               accumulation into a (y,c) SMEM tile, coalesced full writes
// ---------------------------------------------------------------------------

#define C_IN    64
#define C_OUT   64
#define BEV_Y   256
#define BEV_XY  (256 * 256)
#define TILE_P  128
#define NZ      32
#define NBX     1024
#define N_MAX   (1 << 17)
#define B_MAX   224
#define TILES_MAX (N_MAX / TILE_P + NZ + 2)
#define FSN     132
#define KEYS_CHUNK 512

#define SMEM_GEMM_BYTES ((4096 + 64 * FSN) * 4)

// ---- scratch (static device globals) ----
__device__ int   g_blkz[B_MAX * NZ];
__device__ int   g_offz[B_MAX * NZ];
__device__ int   g_blkbx[B_MAX * NBX];
__device__ int   g_offbx[B_MAX * NBX];
__device__ int   g_bxstart[NBX];
__device__ int   g_bxcnt[NBX];
__device__ int   g_ntiles;
__device__ int   g_pidx[N_MAX];            // z-sorted -> original point index
__device__ int   g_okey[N_MAX];            // bx-sorted -> (zpos<<8) | y
__device__ float g_inter[(size_t)N_MAX * C_OUT];   // 32 MB
__device__ int   g_tile_z[TILES_MAX];
__device__ int   g_tile_start[TILES_MAX];
__device__ int   g_tile_cnt[TILES_MAX];

// ---------------------------------------------------------------------------
__device__ __forceinline__ int detect_is64_warp(const void* coords) {
    const long long* c = (const long long*)coords;
    bool hz = ((c[threadIdx.x & 31] >> 32) == 0);
    unsigned m = __ballot_sync(0xffffffffu, hz);
    return (m == 0xffffffffu) ? 1 : 0;
}

__device__ __forceinline__ void load_coord4(const void* coords, int is64, int i,
                                            int& x, int& z, int& y, int& b) {
    if (is64) {
        const long long* p = (const long long*)coords + 4ll * i;
        x = (int)p[0]; z = (int)p[1]; y = (int)p[2]; b = (int)p[3];
    } else {
        const int* p = (const int*)coords + 4 * i;
        x = p[0]; z = p[1]; y = p[2]; b = p[3];
    }
}

// ---------------------------------------------------------------------------
// Dual histogram: z buckets (32) and bx buckets (1024). SMEM atomics only.
// ---------------------------------------------------------------------------
__global__ void k_hist(const void* coords, const int* stride_p, int n, int chunk) {
    __shared__ int hz[NZ];
    __shared__ int hbx[NBX];
    __shared__ int s_is64;
    int tid = threadIdx.x;
    if (tid < NZ) hz[tid] = 0;
    for (int t = tid; t < NBX; t += 256) hbx[t] = 0;
    if (tid < 32) {
        int v = detect_is64_warp(coords);
        if (tid == 0) s_is64 = v;
    }
    __syncthreads();

    int stride = max(*stride_p, 1);
    int lo = blockIdx.x * chunk;
    int hi = min(lo + chunk, n);
    int is64 = s_is64;
    for (int i = lo + tid; i < hi; i += 256) {
        int x, z, y, b;
        load_coord4(coords, is64, i, x, z, y, b);
        atomicAdd(&hz[z / stride], 1);
        int bx = (b << 8) | (x / stride);
        atomicAdd(&hbx[bx & (NBX - 1)], 1);
    }
    __syncthreads();
    if (tid < NZ) g_blkz[blockIdx.x * NZ + tid] = hz[tid];
    for (int t = tid; t < NBX; t += 256)
        g_blkbx[blockIdx.x * NBX + t] = hbx[t];
}

// ---------------------------------------------------------------------------
// Single-block scan for both sorts + tile descriptors. 1024 threads.
// ---------------------------------------------------------------------------
__global__ void k_scan(int B) {
    __shared__ int s[B_MAX * NZ];          // 28 KB
    __shared__ int bstart[NZ];
    __shared__ int bcnt[NZ];
    __shared__ int tstart[NZ + 1];
    __shared__ int wsum[32];
    int tid = threadIdx.x;

    // ---- part A: z sort ----
    for (int t = tid; t < B * NZ; t += 1024) s[t] = g_blkz[t];
    __syncthreads();

    if (tid < NZ) {
        int z = tid, run = 0;
        for (int b = 0; b < B; b++) {
            int v = s[b * NZ + z];
            s[b * NZ + z] = run;
            run += v;
        }
        bcnt[z] = run;
    }
    __syncthreads();

    if (tid < 32) {
        int z = tid;
        int c  = bcnt[z];
        int tl = (c + TILE_P - 1) / TILE_P;
        int co = c, to = tl;
        #pragma unroll
        for (int d = 1; d < 32; d <<= 1) {
            int v = __shfl_up_sync(0xffffffffu, co, d);
            int w = __shfl_up_sync(0xffffffffu, to, d);
            if (z >= d) { co += v; to += w; }
        }
        bstart[z] = co - c;
        tstart[z] = to - tl;
        if (z == 31) { tstart[NZ] = to; g_ntiles = to; }
    }
    __syncthreads();

    for (int t = tid; t < B * NZ; t += 1024) {
        int z = t & (NZ - 1);
        g_offz[t] = s[t] + bstart[z];
    }

    int ntiles = tstart[NZ];
    for (int t = tid; t < ntiles; t += 1024) {
        int lo = 0, hi = NZ - 1;
        while (lo < hi) {
            int mid = (lo + hi + 1) >> 1;
            if (tstart[mid] <= t) lo = mid; else hi = mid - 1;
        }
        int local = t - tstart[lo];
        g_tile_z[t]     = lo;
        g_tile_start[t] = bstart[lo] + local * TILE_P;
        g_tile_cnt[t]   = min(TILE_P, bcnt[lo] - local * TILE_P);
    }

    // ---- part B: bx sort (thread tid owns bucket tid) ----
    int run = 0;
    for (int b = 0; b < B; b++) {
        int v = g_blkbx[b * NBX + tid];
        g_offbx[b * NBX + tid] = run;
        run += v;
    }
    g_bxcnt[tid] = run;

    // block-wide exclusive scan of 1024 bucket counts
    int lane = tid & 31, w = tid >> 5;
    int inc = run;
    #pragma unroll
    for (int d = 1; d < 32; d <<= 1) {
        int v = __shfl_up_sync(0xffffffffu, inc, d);
        if (lane >= d) inc += v;
    }
    if (lane == 31) wsum[w] = inc;
    __syncthreads();
    if (w == 0) {
        int v = wsum[lane];
        int iv = v;
        #pragma unroll
        for (int d = 1; d < 32; d <<= 1) {
            int u = __shfl_up_sync(0xffffffffu, iv, d);
            if (lane >= d) iv += u;
        }
        wsum[lane] = iv - v;   // exclusive
    }
    __syncthreads();
    g_bxstart[tid] = wsum[w] + inc - run;
}

// ---------------------------------------------------------------------------
// Counting-sort scatter for both orders.
// ---------------------------------------------------------------------------
__global__ void k_scatter(const void* coords, const int* stride_p, int n, int chunk) {
    __shared__ int cur_z[NZ];
    __shared__ int cur_bx[NBX];
    __shared__ int s_is64;
    int tid = threadIdx.x;
    if (tid < NZ) cur_z[tid] = g_offz[blockIdx.x * NZ + tid];
    for (int t = tid; t < NBX; t += 256)
        cur_bx[t] = g_bxstart[t] + g_offbx[blockIdx.x * NBX + t];
    if (tid < 32) {
        int v = detect_is64_warp(coords);
        if (tid == 0) s_is64 = v;
    }
    __syncthreads();

    int stride = max(*stride_p, 1);
    int lo = blockIdx.x * chunk;
    int hi = min(lo + chunk, n);
    int is64 = s_is64;
    for (int i = lo + tid; i < hi; i += 256) {
        int x, z, y, b;
        load_coord4(coords, is64, i, x, z, y, b);
        int zq = z / stride;
        int xq = x / stride;
        int yq = y / stride;
        int bx = ((b << 8) | xq) & (NBX - 1);

        int zpos = atomicAdd(&cur_z[zq], 1);
        g_pidx[zpos] = i;
        int bxpos = atomicAdd(&cur_bx[bx], 1);
        g_okey[bxpos] = (zpos << 8) | (yq & 255);
    }
}

// ---------------------------------------------------------------------------
// GEMM: one block = one tile of up to 128 points sharing kernel z.
// 128 threads, 8x8 register block, coalesced float4 stores into g_inter.
// ---------------------------------------------------------------------------
__global__ __launch_bounds__(128, 4)
void k_gemm(const float* __restrict__ features,
            const float* __restrict__ kern) {
    int tile = blockIdx.x;
    if (tile >= g_ntiles) return;

    extern __shared__ float smem[];
    float* Ks = smem;                 // [64][64]
    float* Fs = smem + 4096;          // [64][FSN]

    int tid   = threadIdx.x;
    int z     = g_tile_z[tile];
    int start = g_tile_start[tile];
    int cnt   = g_tile_cnt[tile];

    bool valid = tid < cnt;
    int pidx = valid ? g_pidx[start + tid] : 0;

    {
        const float4* k4 = (const float4*)(kern + (size_t)z * C_IN * C_OUT);
        float4* ks4 = (float4*)Ks;
        #pragma unroll
        for (int t = 0; t < 8; t++) ks4[tid + t * 128] = k4[tid + t * 128];
    }
    {
        const float4* frow = (const float4*)(features + (size_t)pidx * C_IN);
        #pragma unroll
        for (int g = 0; g < 16; g++) {
            float4 f = valid ? frow[g] : make_float4(0.f, 0.f, 0.f, 0.f);
            int r = g * 4;
            Fs[(r + 0) * FSN + tid] = f.x;
            Fs[(r + 1) * FSN + tid] = f.y;
            Fs[(r + 2) * FSN + tid] = f.z;
            Fs[(r + 3) * FSN + tid] = f.w;
        }
    }
    __syncthreads();

    int tc = tid & 7;     // channel group (8 x 8 channels)
    int tp = tid >> 3;    // point group  (16 x 8 points)

    float acc[8][8];
    #pragma unroll
    for (int a = 0; a < 8; a++)
        #pragma unroll
        for (int c = 0; c < 8; c++) acc[a][c] = 0.f;

    const float4* fsA = (const float4*)&Fs[tp * 8];
    const float4* ksB = (const float4*)&Ks[tc * 8];

    #pragma unroll 8
    for (int i = 0; i < C_IN; i++) {
        float4 a0 = fsA[i * (FSN / 4)];
        float4 a1 = fsA[i * (FSN / 4) + 1];
        float4 b0 = ksB[i * (C_OUT / 4)];
        float4 b1 = ksB[i * (C_OUT / 4) + 1];
        float av[8] = {a0.x, a0.y, a0.z, a0.w, a1.x, a1.y, a1.z, a1.w};
        float bv[8] = {b0.x, b0.y, b0.z, b0.w, b1.x, b1.y, b1.z, b1.w};
        #pragma unroll
        for (int p = 0; p < 8; p++)
            #pragma unroll
            for (int c = 0; c < 8; c++)
                acc[p][c] += av[p] * bv[c];
    }

    // coalesced stores: point row 256B covered by 8 threads x 2 float4
    #pragma unroll
    for (int pp = 0; pp < 8; pp++) {
        int p = tp * 8 + pp;
        if (p >= cnt) continue;
        float* row = &g_inter[(size_t)(start + p) * C_OUT + tc * 8];
        ((float4*)row)[0] = make_float4(acc[pp][0], acc[pp][1], acc[pp][2], acc[pp][3]);
        ((float4*)row)[1] = make_float4(acc[pp][4], acc[pp][5], acc[pp][6], acc[pp][7]);
    }
}

// ---------------------------------------------------------------------------
// Output: one block per (b, x, channel-half). Keys staged through SMEM,
// inter-row loads batched 4-deep for MLP, SMEM (y,c) accumulation, then
// fully-coalesced writes covering every output element (zeros included).
// ---------------------------------------------------------------------------
__global__ __launch_bounds__(256, 6)
void k_out(float* __restrict__ out) {
    __shared__ float acc[256 * 33];        // [y][c-half], pad 33 vs 32
    __shared__ int   keys[KEYS_CHUNK];
    int tid  = threadIdx.x;
    int bb   = blockIdx.x >> 1;            // (b,x) bucket
    int half = blockIdx.x & 1;             // channel half
    int b    = bb >> 8;
    int x    = bb & 255;

    for (int i = tid; i < 256 * 33; i += 256) acc[i] = 0.f;

    int start = g_bxstart[bb];
    int cnt   = g_bxcnt[bb];
    int lane  = tid & 31;                  // channel within half
    int grp   = tid >> 5;                  // 8 point-groups
    int c     = half * 32 + lane;

    for (int base = 0; base < cnt; base += KEYS_CHUNK) {
        int m = min(KEYS_CHUNK, cnt - base);
        __syncthreads();
        for (int i = tid; i < m; i += 256) keys[i] = g_okey[start + base + i];
        __syncthreads();

        // group 'grp' handles points p ≡ grp (mod 8); 4 in flight per batch
        for (int p0 = grp; p0 < m; p0 += 32) {
            float v[4];
            int   yy[4];
            #pragma unroll
            for (int j = 0; j < 4; j++) {
                int p = p0 + j * 8;
                if (p < m) {
                    int key = keys[p];
                    yy[j] = key & 255;
                    v[j]  = g_inter[(size_t)(key >> 8) * C_OUT + c];
                } else {
                    yy[j] = -1;
                    v[j]  = 0.f;
                }
            }
            #pragma unroll
            for (int j = 0; j < 4; j++)
                if (yy[j] >= 0) atomicAdd(&acc[yy[j] * 33 + lane], v[j]);
        }
    }
    __syncthreads();

    // write out[b][half*32 + k][x][y=tid] for k = 0..31, coalesced 1KB rows
    size_t outbase = ((size_t)b * C_OUT + half * 32) * BEV_XY + (size_t)x * 256;
    #pragma unroll 4
    for (int k = 0; k < 32; k++)
        out[outbase + (size_t)k * BEV_XY + tid] = acc[tid * 33 + k];
}

// ---------------------------------------------------------------------------
extern "C" void kernel_launch(void* const* d_in, const int* in_sizes, int n_in,
                              void* d_out, int out_size) {
    const float* features = (const float*)d_in[0];
    const float* kern     = (const float*)d_in[1];
    const void*  coords   = (const void*)d_in[2];
    const int*   stride_p = (const int*)d_in[3];
    float* out = (float*)d_out;

    int n = in_sizes[0] / C_IN;
    if (n > N_MAX) n = N_MAX;
    if (n < 1) return;

    int B = (n + 255) / 256;
    if (B > B_MAX) B = B_MAX;
    if (B < 1) B = 1;
    int chunk = (((n + B - 1) / B) + 255) & ~255;
    B = (n + chunk - 1) / chunk;

    static int attr_set = 0;
    if (!attr_set) {
        cudaFuncSetAttribute(k_gemm, cudaFuncAttributeMaxDynamicSharedMemorySize,
                             SMEM_GEMM_BYTES);
        attr_set = 1;
    }

    int nbx = out_size / (C_OUT * 256);    // (b,x) buckets in this problem
    if (nbx > NBX) nbx = NBX;

    k_hist<<<B, 256>>>(coords, stride_p, n, chunk);
    k_scan<<<1, 1024>>>(B);
    k_scatter<<<B, 256>>>(coords, stride_p, n, chunk);

    int max_tiles = n / TILE_P + NZ + 1;
    k_gemm<<<max_tiles, 128, SMEM_GEMM_BYTES>>>(features, kern);
    k_out<<<nbx * 2, 256>>>(out);
}